// round 15
// baseline (speedup 1.0000x reference)
#include <cuda_runtime.h>
#include <cuda_bf16.h>
#include <cuda_fp16.h>
#include <cstdint>

// Problem constants
#define Bb 2
#define Tt 2048
#define Cc 1280
#define Hh 10
#define Dd 128
#define Mtot (Bb*Tt)          // 4096
#define WSZ (Cc*Cc)
#define BH (Bb*Hh)            // 20
#define SOFT_SCALE 0.08838834764831845f  // 1/sqrt(128)

// Scratch (device globals; allocation-free rule)
__device__ uint32_t g_xf[Mtot*Cc/2];     // x in fp16 (half2 packed)
__device__ uint32_t g_wf[4*WSZ/2];       // Wq,Wk,Wv,Wproj in fp16
__device__ uint32_t g_atf[Mtot*Cc/2];    // attention out fp16 [b,t,h,d]
__device__ uint32_t g_qf[BH*Tt*Dd/2];    // q fp16 pairs, pre-scaled
__device__ uint32_t g_kf[BH*Tt*Dd/2];    // k fp16 pairs
__device__ uint32_t g_vt[BH*Dd*Tt/2];    // v fp16, [bh][d][t-pair]
__device__ float    g_po[2*BH*Tt*Dd];    // split-KV partial O (fp32)
__device__ float    g_pml[2*BH*Tt*2];    // split-KV partial (m, l)

// ---------------------------------------------------------------------------
// Helpers
// ---------------------------------------------------------------------------
#define F16_MMA(d, a, b) \
    asm volatile( \
        "mma.sync.aligned.m16n8k16.row.col.f32.f16.f16.f32 " \
        "{%0,%1,%2,%3}, {%4,%5,%6,%7}, {%8,%9}, {%0,%1,%2,%3};\n" \
        : "+f"(d[0]), "+f"(d[1]), "+f"(d[2]), "+f"(d[3]) \
        : "r"(a[0]), "r"(a[1]), "r"(a[2]), "r"(a[3]), "r"(b[0]), "r"(b[1]))

#define LDSM4(r0, r1, r2, r3, addr) \
    asm volatile("ldmatrix.sync.aligned.m8n8.x4.shared.b16 {%0,%1,%2,%3}, [%4];" \
        : "=r"(r0), "=r"(r1), "=r"(r2), "=r"(r3) : "r"(addr))

#define CP_ASYNC16(dst, src) \
    asm volatile("cp.async.cg.shared.global [%0], [%1], 16;" \
        :: "r"(dst), "l"(src))
#define CP_COMMIT() asm volatile("cp.async.commit_group;" ::: "memory")
#define CP_WAIT(n)  asm volatile("cp.async.wait_group %0;" :: "n"(n) : "memory")

__device__ __forceinline__ uint32_t s2u(const void* p) {
    uint32_t a;
    asm("{ .reg .u64 t; cvta.to.shared.u64 t, %1; cvt.u32.u64 %0, t; }"
        : "=r"(a) : "l"(p));
    return a;
}

__device__ __forceinline__ uint32_t packh2(float x, float y) {
    __half2 p = __floats2half2_rn(x, y);
    return *reinterpret_cast<uint32_t*>(&p);
}

// ---------------------------------------------------------------------------
// fp32 -> fp16 converts
// ---------------------------------------------------------------------------
__global__ __launch_bounds__(256) void cvt_f16_kernel(
    const float* __restrict__ src, uint32_t* __restrict__ dst, int n4)
{
    int i = blockIdx.x * 256 + threadIdx.x;
    if (i >= n4) return;
    float4 v = *(const float4*)(src + 4 * (long)i);
    dst[2 * i]     = packh2(v.x, v.y);
    dst[2 * i + 1] = packh2(v.z, v.w);
}

__global__ __launch_bounds__(256) void cvt_w_kernel(
    const float* __restrict__ w0, const float* __restrict__ w1,
    const float* __restrict__ w2, const float* __restrict__ w3)
{
    int i = blockIdx.x * 256 + threadIdx.x;
    const float* src = (blockIdx.y == 0) ? w0 : (blockIdx.y == 1) ? w1
                      : (blockIdx.y == 2) ? w2 : w3;
    uint32_t* dst = g_wf + (long)blockIdx.y * (WSZ / 2);
    float4 v = *(const float4*)(src + 4 * (long)i);
    dst[2 * i]     = packh2(v.x, v.y);
    dst[2 * i + 1] = packh2(v.z, v.w);
}

// ---------------------------------------------------------------------------
// fp16 GEMM with fused rope/rms/vpack epilogues (R14-verified, untouched)
// ---------------------------------------------------------------------------
#define STRB 80
#define OFF_A 0
#define OFF_B (128*STRB)
#define STAGE_B (2*128*STRB)      // 20480
#define GEMM_SMEM (4*STAGE_B)     // 81920
#define SMF_S 133

__global__ __launch_bounds__(256, 2) void gemm_f16(
    const uint32_t* __restrict__ A_u,
    float* __restrict__ Out,
    const float* __restrict__ cosp,
    const float* __restrict__ sinp,
    int mode)
{
    extern __shared__ char smc[];
    const uint32_t sb = s2u(smc);

    const int tid  = threadIdx.x;
    const int warp = tid >> 5;
    const int lane = tid & 31;
    const int wm = warp & 1;
    const int wn = warp >> 1;
    const int gid = lane >> 2;
    const int tig = lane & 3;

    const int m0 = blockIdx.y * 128;
    const int n0 = blockIdx.x * 128;
    const int z  = (mode == 0) ? 3 : blockIdx.z;

    const __half* A_g = (const __half*)A_u;
    const __half* W_g = (const __half*)(g_wf) + (long)z * WSZ;

    const int ch0_row = tid >> 2,          ch0_kc = tid & 3;
    const int ch1_row = (tid + 256) >> 2,  ch1_kc = tid & 3;

    float acc[4][4][4];
#pragma unroll
    for (int mi = 0; mi < 4; mi++)
#pragma unroll
        for (int ni = 0; ni < 4; ni++)
#pragma unroll
            for (int c = 0; c < 4; c++) acc[mi][ni][c] = 0.f;

    const int NCH = Cc / 32;   // 40

    auto issue_stage = [&](int stage, int buf) {
        const int kc0 = stage * 32;
        const uint32_t stB = sb + buf * STAGE_B;
        {
            uint32_t so = ch0_row * STRB + ch0_kc * 16;
            long ga = (long)(m0 + ch0_row) * Cc + kc0 + ch0_kc * 8;
            long gb = (long)(n0 + ch0_row) * Cc + kc0 + ch0_kc * 8;
            CP_ASYNC16(stB + OFF_A + so, A_g + ga);
            CP_ASYNC16(stB + OFF_B + so, W_g + gb);
        }
        {
            uint32_t so = ch1_row * STRB + ch1_kc * 16;
            long ga = (long)(m0 + ch1_row) * Cc + kc0 + ch1_kc * 8;
            long gb = (long)(n0 + ch1_row) * Cc + kc0 + ch1_kc * 8;
            CP_ASYNC16(stB + OFF_A + so, A_g + ga);
            CP_ASYNC16(stB + OFF_B + so, W_g + gb);
        }
        CP_COMMIT();
    };

    const uint32_t aRow = wm * 64 + (lane & 7) + ((lane >> 3) & 1) * 8;
    const uint32_t aOff = aRow * STRB + (lane >> 4) * 16;
    const uint32_t bRow = wn * 32 + (lane & 7) + ((lane >> 4) << 3);
    const uint32_t bOff = bRow * STRB + ((lane >> 3) & 1) * 16;

    issue_stage(0, 0);
    issue_stage(1, 1);
    issue_stage(2, 2);

    for (int c = 0; c < NCH; c++) {
        if (c + 3 < NCH) issue_stage(c + 3, (c + 3) & 3);
        else             CP_COMMIT();
        CP_WAIT(3);
        __syncthreads();

        const uint32_t base = sb + (c & 3) * STAGE_B;
#pragma unroll
        for (int kk = 0; kk < 2; kk++) {
            const uint32_t ko = kk * 32;
            uint32_t b[4][2];
#pragma unroll
            for (int p = 0; p < 2; p++) {
                uint32_t t0, t1, t2, t3;
                LDSM4(t0, t1, t2, t3, base + OFF_B + bOff + p * (16 * STRB) + ko);
                b[2 * p][0] = t0;     b[2 * p][1] = t1;
                b[2 * p + 1][0] = t2; b[2 * p + 1][1] = t3;
            }
#pragma unroll
            for (int mi = 0; mi < 4; mi++) {
                uint32_t a[4];
                LDSM4(a[0], a[1], a[2], a[3],
                      base + OFF_A + aOff + mi * (16 * STRB) + ko);
#pragma unroll
                for (int ni = 0; ni < 4; ni++)
                    F16_MMA(acc[mi][ni], a, b[ni]);
            }
        }
        __syncthreads();
    }

    if (mode == 0) {
#pragma unroll
        for (int mi = 0; mi < 4; mi++) {
#pragma unroll
            for (int ni = 0; ni < 4; ni++) {
                int r_lo = m0 + wm * 64 + mi * 16 + gid;
                int cn = n0 + wn * 32 + ni * 8 + 2 * tig;
                *(float2*)(Out + (long)r_lo * Cc + cn) =
                    make_float2(acc[mi][ni][0], acc[mi][ni][1]);
                *(float2*)(Out + (long)(r_lo + 8) * Cc + cn) =
                    make_float2(acc[mi][ni][2], acc[mi][ni][3]);
            }
        }
        return;
    }

    // fused q/k/v epilogue
    float* smf = (float*)smc;
#pragma unroll
    for (int mi = 0; mi < 4; mi++)
#pragma unroll
        for (int ni = 0; ni < 4; ni++) {
            int rl = wm * 64 + mi * 16 + gid;
            int cl = wn * 32 + ni * 8 + 2 * tig;
            smf[rl * SMF_S + cl]           = acc[mi][ni][0];
            smf[rl * SMF_S + cl + 1]       = acc[mi][ni][1];
            smf[(rl + 8) * SMF_S + cl]     = acc[mi][ni][2];
            smf[(rl + 8) * SMF_S + cl + 1] = acc[mi][ni][3];
        }
    __syncthreads();

    const int h_ = n0 >> 7;
    if (z <= 1) {
        uint32_t* dst = (z == 0) ? g_qf : g_kf;
#pragma unroll 1
        for (int pass = 0; pass < 16; pass++) {
            int row = pass * 8 + warp;
            int m = m0 + row;
            int t = m & (Tt - 1);
            int b_ = m >> 11;
            const float* pr = smf + row * SMF_S;
            float a0 = pr[2 * lane],      a1 = pr[2 * lane + 1];
            float a2 = pr[64 + 2 * lane], a3 = pr[64 + 2 * lane + 1];
            float2 cc  = *(const float2*)(cosp + t * 64 + 2 * lane);
            float2 ss2 = *(const float2*)(sinp + t * 64 + 2 * lane);

            float y0 =  a0 * cc.x + a2 * ss2.x;
            float y2 = -a0 * ss2.x + a2 * cc.x;
            float y1 =  a1 * cc.y + a3 * ss2.y;
            float y3 = -a1 * ss2.y + a3 * cc.y;

            float ss = y0 * y0 + y1 * y1 + y2 * y2 + y3 * y3;
#pragma unroll
            for (int o2 = 16; o2; o2 >>= 1)
                ss += __shfl_xor_sync(0xFFFFFFFFu, ss, o2);
            float inv = rsqrtf(ss * (1.0f / 128.0f) + 1e-5f);
            if (z == 0) inv *= SOFT_SCALE;

            long rowg = ((long)(b_ * Hh + h_)) * Tt + t;
            dst[rowg * 64 + lane]      = packh2(y0 * inv, y1 * inv);
            dst[rowg * 64 + 32 + lane] = packh2(y2 * inv, y3 * inv);
        }
    } else {
        int b_ = m0 >> 11;
        int t0 = m0 & (Tt - 1);
        uint32_t* vdst = g_vt + ((long)(b_ * Hh + h_)) * Dd * (Tt / 2) + (t0 >> 1);
        for (int idx = tid; idx < 8192; idx += 256) {
            int d = idx >> 6, tp = idx & 63;
            vdst[(long)d * (Tt / 2) + tp] =
                packh2(smf[(2 * tp) * SMF_S + d], smf[(2 * tp + 1) * SMF_S + d]);
        }
    }
}

// ---------------------------------------------------------------------------
// Flash attention, split-KV: block (qtile, half) processes half the key range
// and writes un-normalized partials (o, m, l). Mainloop R13-verified.
// ---------------------------------------------------------------------------
#define FQP 68
#define FVP 36
#define FQPB (FQP*4)
#define FVPB (FVP*4)
#define KSTG (64*FQP)
#define VSTG (128*FVP)
#define FLASH_SMEM_BYTES ((128*FQP + 2*KSTG + 2*VSTG) * 4)   // 106,496

__global__ __launch_bounds__(256, 2) void flash_f16_kernel()
{
    extern __shared__ uint32_t smu[];
    uint32_t* Qf = smu;                          // [128][68]
    const uint32_t sbase = s2u(smu);

    const int tid  = threadIdx.x;
    const int wid  = tid >> 5;
    const int lane = tid & 31;
    const int gid  = lane >> 2;
    const int tig  = lane & 3;

    const int qtile = 15 - (blockIdx.x >> 1);    // heavy tiles first
    const int half  = blockIdx.x & 1;
    const int bh = blockIdx.y;
    const uint32_t* qsrc = g_qf + (long)bh * Tt * 64;
    const uint32_t* ksrc = g_kf + (long)bh * Tt * 64;
    const uint32_t* vsrc = g_vt + (long)bh * Dd * (Tt / 2);
    const int qb0 = qtile * 128;
    const int kt0 = half ? (qtile + 1) : 0;
    const int kt1 = half ? (2 * qtile + 2) : (qtile + 1);

    const uint32_t kst_b = sbase + 128 * FQP * 4;
    const uint32_t vst_b = kst_b + 2 * KSTG * 4;

    auto issue_kv = [&](int kt, int buf) {
        const int kbase = kt * 64;
#pragma unroll
        for (int i = 0; i < 4; i++) {
            int c = tid + i * 256;
            int r = c >> 4, col = (c & 15) << 2;
            CP_ASYNC16(kst_b + (buf * KSTG + r * FQP + col) * 4,
                       ksrc + (long)(kbase + r) * 64 + col);
        }
#pragma unroll
        for (int i = 0; i < 4; i++) {
            int c = tid + i * 256;
            int d = c >> 3, col = (c & 7) << 2;
            CP_ASYNC16(vst_b + (buf * VSTG + d * FVP + col) * 4,
                       vsrc + (long)d * (Tt / 2) + (kbase >> 1) + col);
        }
        CP_COMMIT();
    };

    for (int idx = tid; idx < 2048; idx += 256) {
        int r = idx >> 4, c = (idx & 15) << 2;
        uint4 v = *(const uint4*)(qsrc + (long)(qb0 + r) * 64 + c);
        *(uint4*)(Qf + r * FQP + c) = v;
    }

    issue_kv(kt0, kt0 & 1);

    float o[16][4];
    float m_[2], l_[2];
#pragma unroll
    for (int ni = 0; ni < 16; ni++)
#pragma unroll
        for (int c = 0; c < 4; c++) o[ni][c] = 0.f;
    m_[0] = m_[1] = -1e30f;
    l_[0] = l_[1] = 0.f;

    const int qrow = wid * 16;

    const uint32_t qOff = (uint32_t)(qrow + (lane & 7) + ((lane >> 3) & 1) * 8) * FQPB
                        + (uint32_t)(lane >> 4) * 16;
    const uint32_t kOff = (uint32_t)((lane & 7) + ((lane >> 4) << 3)) * FQPB
                        + (uint32_t)((lane >> 3) & 1) * 16;
    const uint32_t vOff = (uint32_t)((lane & 7) + ((lane >> 4) << 3)) * FVPB
                        + (uint32_t)((lane >> 3) & 1) * 16;

    for (int kt = kt0; kt < kt1; kt++) {
        if (kt + 1 < kt1) { issue_kv(kt + 1, (kt + 1) & 1); CP_WAIT(1); }
        else              { CP_WAIT(0); }
        __syncthreads();

        const int kbase = kt * 64;
        const uint32_t kf_b = kst_b + (uint32_t)(kt & 1) * KSTG * 4;
        const uint32_t vt_b = vst_b + (uint32_t)(kt & 1) * VSTG * 4;

        float s[8][4];
#pragma unroll
        for (int t = 0; t < 8; t++)
#pragma unroll
            for (int c = 0; c < 4; c++) s[t][c] = 0.f;

#pragma unroll
        for (int j = 0; j < 8; j++) {
            uint32_t a[4];
            LDSM4(a[0], a[1], a[2], a[3], sbase + qOff + j * 32);
            uint32_t b[8][2];
#pragma unroll
            for (int p = 0; p < 4; p++) {
                uint32_t t0, t1, t2, t3;
                LDSM4(t0, t1, t2, t3, kf_b + kOff + p * (16 * FQPB) + j * 32);
                b[2 * p][0] = t0;     b[2 * p][1] = t1;
                b[2 * p + 1][0] = t2; b[2 * p + 1][1] = t3;
            }
#pragma unroll
            for (int ni = 0; ni < 8; ni++)
                F16_MMA(s[ni], a, b[ni]);
        }

        if (kt >= 2 * qtile) {
            int r0g = qb0 + qrow + gid;
#pragma unroll
            for (int t = 0; t < 8; t++) {
                int col = kbase + 8 * t + 2 * tig;
                if (col     > r0g)     s[t][0] = -1e30f;
                if (col + 1 > r0g)     s[t][1] = -1e30f;
                if (col     > r0g + 8) s[t][2] = -1e30f;
                if (col + 1 > r0g + 8) s[t][3] = -1e30f;
            }
        }

#pragma unroll
        for (int r = 0; r < 2; r++) {
            float mx = -1e30f;
#pragma unroll
            for (int t = 0; t < 8; t++)
                mx = fmaxf(mx, fmaxf(s[t][2 * r], s[t][2 * r + 1]));
            mx = fmaxf(mx, __shfl_xor_sync(0xFFFFFFFFu, mx, 1));
            mx = fmaxf(mx, __shfl_xor_sync(0xFFFFFFFFu, mx, 2));
            float mn = fmaxf(m_[r], mx);
            float alpha = __expf(m_[r] - mn);
            float sum = 0.f;
#pragma unroll
            for (int t = 0; t < 8; t++) {
                float p0 = __expf(s[t][2 * r]     - mn);
                float p1 = __expf(s[t][2 * r + 1] - mn);
                s[t][2 * r] = p0; s[t][2 * r + 1] = p1;
                sum += p0 + p1;
            }
            sum += __shfl_xor_sync(0xFFFFFFFFu, sum, 1);
            sum += __shfl_xor_sync(0xFFFFFFFFu, sum, 2);
            l_[r] = l_[r] * alpha + sum;
            m_[r] = mn;
#pragma unroll
            for (int ni = 0; ni < 16; ni++) {
                o[ni][2 * r]     *= alpha;
                o[ni][2 * r + 1] *= alpha;
            }
        }

#pragma unroll
        for (int j = 0; j < 4; j++) {
            uint32_t a[4];
            a[0] = packh2(s[2 * j][0],     s[2 * j][1]);
            a[1] = packh2(s[2 * j][2],     s[2 * j][3]);
            a[2] = packh2(s[2 * j + 1][0], s[2 * j + 1][1]);
            a[3] = packh2(s[2 * j + 1][2], s[2 * j + 1][3]);
#pragma unroll
            for (int p = 0; p < 8; p++) {
                uint32_t t0, t1, t2, t3;
                LDSM4(t0, t1, t2, t3, vt_b + vOff + p * (16 * FVPB) + j * 32);
                uint32_t b0[2] = {t0, t1};
                uint32_t b1[2] = {t2, t3};
                F16_MMA(o[2 * p],     a, b0);
                F16_MMA(o[2 * p + 1], a, b1);
            }
        }
        __syncthreads();
    }

    // ---- epilogue: write un-normalized partials + (m, l) ----
    int r0g = qb0 + qrow + gid;
    long prow0 = (long)(half * BH + bh) * Tt + r0g;
    long prow1 = prow0 + 8;
    float* po0 = g_po + prow0 * Dd;
    float* po1 = g_po + prow1 * Dd;
#pragma unroll
    for (int ni = 0; ni < 16; ni++) {
        int d = 8 * ni + 2 * tig;
        *(float2*)(po0 + d) = make_float2(o[ni][0], o[ni][1]);
        *(float2*)(po1 + d) = make_float2(o[ni][2], o[ni][3]);
    }
    if (tig == 0) {
        g_pml[prow0 * 2]     = m_[0];
        g_pml[prow0 * 2 + 1] = l_[0];
        g_pml[prow1 * 2]     = m_[1];
        g_pml[prow1 * 2 + 1] = l_[1];
    }
}

// ---------------------------------------------------------------------------
// Split-KV combine: merge the two partials per row, write fp16 g_atf.
// ---------------------------------------------------------------------------
__global__ __launch_bounds__(256) void combine_kernel()
{
    int idx = blockIdx.x * 256 + threadIdx.x;   // 655,360 threads
    int row = idx >> 4;                         // 0 .. BH*Tt-1
    int dseg = (idx & 15) << 3;                 // 0,8,..,120
    int bh = row >> 11, t = row & (Tt - 1);
    int b_ = bh / Hh, h_ = bh % Hh;

    long p0 = (long)bh * Tt + t;
    long p1 = (long)(BH + bh) * Tt + t;
    float m0 = g_pml[p0 * 2], l0 = g_pml[p0 * 2 + 1];
    float m1 = g_pml[p1 * 2], l1 = g_pml[p1 * 2 + 1];
    float m = fmaxf(m0, m1);
    float w0 = __expf(m0 - m), w1 = __expf(m1 - m);
    float invl = 1.f / (l0 * w0 + l1 * w1);

    const float* o0 = g_po + p0 * Dd + dseg;
    const float* o1 = g_po + p1 * Dd + dseg;
    float4 a0 = *(const float4*)(o0);
    float4 a1 = *(const float4*)(o0 + 4);
    float4 c0 = *(const float4*)(o1);
    float4 c1 = *(const float4*)(o1 + 4);

    uint4 out;
    out.x = packh2((a0.x * w0 + c0.x * w1) * invl, (a0.y * w0 + c0.y * w1) * invl);
    out.y = packh2((a0.z * w0 + c0.z * w1) * invl, (a0.w * w0 + c0.w * w1) * invl);
    out.z = packh2((a1.x * w0 + c1.x * w1) * invl, (a1.y * w0 + c1.y * w1) * invl);
    out.w = packh2((a1.z * w0 + c1.z * w1) * invl, (a1.w * w0 + c1.w * w1) * invl);

    *(uint4*)(g_atf + ((((long)(b_ * Tt + t)) * Cc + h_ * Dd + dseg) >> 1)) = out;
}

// ---------------------------------------------------------------------------
extern "C" void kernel_launch(void* const* d_in, const int* in_sizes, int n_in,
                              void* d_out, int out_size)
{
    const float* x    = (const float*)d_in[0];
    const float* cosp = (const float*)d_in[1];
    const float* sinp = (const float*)d_in[2];
    const float* Wq   = (const float*)d_in[3];
    const float* Wk   = (const float*)d_in[4];
    const float* Wv   = (const float*)d_in[5];
    const float* Wp   = (const float*)d_in[6];
    float* out = (float*)d_out;

    cudaFuncSetAttribute(gemm_f16,
                         cudaFuncAttributeMaxDynamicSharedMemorySize, GEMM_SMEM);
    cudaFuncSetAttribute(flash_f16_kernel,
                         cudaFuncAttributeMaxDynamicSharedMemorySize,
                         FLASH_SMEM_BYTES);

    uint32_t *xf_p, *atf_p;
    cudaGetSymbolAddress((void**)&xf_p, g_xf);
    cudaGetSymbolAddress((void**)&atf_p, g_atf);

    // 0) Converts
    const int xn4 = Mtot * Cc / 4;
    const int wn4 = WSZ / 4;
    cvt_f16_kernel<<<(xn4 + 255) / 256, 256>>>(x, xf_p, xn4);
    cvt_w_kernel<<<dim3((wn4 + 255) / 256, 4), 256>>>(Wq, Wk, Wv, Wp);

    // 1) Q/K/V projections with fused rope+rmsnorm / vpack
    gemm_f16<<<dim3(Cc / 128, Mtot / 128, 3), 256, GEMM_SMEM>>>(
        xf_p, nullptr, cosp, sinp, 1);
    // 2) Flash attention, split-KV (2 halves per q-tile) + combine
    flash_f16_kernel<<<dim3(32, BH), 256, FLASH_SMEM_BYTES>>>();
    combine_kernel<<<(BH * Tt * 16) / 256, 256>>>();
    // 3) Output projection
    gemm_f16<<<dim3(Cc / 128, Mtot / 128, 1), 256, GEMM_SMEM>>>(
        atf_p, out, nullptr, nullptr, 0);
}

// round 16
// speedup vs baseline: 1.6154x; 1.6154x over previous
#include <cuda_runtime.h>
#include <cuda_bf16.h>
#include <cuda_fp16.h>
#include <cstdint>

// Problem constants
#define Bb 2
#define Tt 2048
#define Cc 1280
#define Hh 10
#define Dd 128
#define Mtot (Bb*Tt)          // 4096
#define WSZ (Cc*Cc)
#define BH (Bb*Hh)            // 20
#define SOFT_SCALE 0.08838834764831845f  // 1/sqrt(128)

// Scratch (device globals; allocation-free rule)
__device__ uint32_t g_xf[Mtot*Cc/2];     // x in fp16 (half2 packed)
__device__ uint32_t g_wf[4*WSZ/2];       // Wq,Wk,Wv,Wproj in fp16
__device__ uint32_t g_atf[Mtot*Cc/2];    // attention out fp16 [b,t,h,d]
__device__ uint32_t g_qf[BH*Tt*Dd/2];    // q fp16 pairs, pre-scaled
__device__ uint32_t g_kf[BH*Tt*Dd/2];    // k fp16 pairs
__device__ uint32_t g_vt[BH*Dd*Tt/2];    // v fp16, [bh][d][t-pair]

// ---------------------------------------------------------------------------
// Helpers
// ---------------------------------------------------------------------------
#define F16_MMA(d, a, b) \
    asm volatile( \
        "mma.sync.aligned.m16n8k16.row.col.f32.f16.f16.f32 " \
        "{%0,%1,%2,%3}, {%4,%5,%6,%7}, {%8,%9}, {%0,%1,%2,%3};\n" \
        : "+f"(d[0]), "+f"(d[1]), "+f"(d[2]), "+f"(d[3]) \
        : "r"(a[0]), "r"(a[1]), "r"(a[2]), "r"(a[3]), "r"(b[0]), "r"(b[1]))

#define LDSM4(r0, r1, r2, r3, addr) \
    asm volatile("ldmatrix.sync.aligned.m8n8.x4.shared.b16 {%0,%1,%2,%3}, [%4];" \
        : "=r"(r0), "=r"(r1), "=r"(r2), "=r"(r3) : "r"(addr))

#define CP_ASYNC16(dst, src) \
    asm volatile("cp.async.cg.shared.global [%0], [%1], 16;" \
        :: "r"(dst), "l"(src))
#define CP_COMMIT() asm volatile("cp.async.commit_group;" ::: "memory")
#define CP_WAIT(n)  asm volatile("cp.async.wait_group %0;" :: "n"(n) : "memory")

__device__ __forceinline__ uint32_t s2u(const void* p) {
    uint32_t a;
    asm("{ .reg .u64 t; cvta.to.shared.u64 t, %1; cvt.u32.u64 %0, t; }"
        : "=r"(a) : "l"(p));
    return a;
}

__device__ __forceinline__ uint32_t packh2(float x, float y) {
    __half2 p = __floats2half2_rn(x, y);
    return *reinterpret_cast<uint32_t*>(&p);
}

// ---------------------------------------------------------------------------
// fp32 -> fp16 converts
// ---------------------------------------------------------------------------
__global__ __launch_bounds__(256) void cvt_f16_kernel(
    const float* __restrict__ src, uint32_t* __restrict__ dst, int n4)
{
    int i = blockIdx.x * 256 + threadIdx.x;
    if (i >= n4) return;
    float4 v = *(const float4*)(src + 4 * (long)i);
    dst[2 * i]     = packh2(v.x, v.y);
    dst[2 * i + 1] = packh2(v.z, v.w);
}

__global__ __launch_bounds__(256) void cvt_w_kernel(
    const float* __restrict__ w0, const float* __restrict__ w1,
    const float* __restrict__ w2, const float* __restrict__ w3)
{
    int i = blockIdx.x * 256 + threadIdx.x;
    const float* src = (blockIdx.y == 0) ? w0 : (blockIdx.y == 1) ? w1
                      : (blockIdx.y == 2) ? w2 : w3;
    uint32_t* dst = g_wf + (long)blockIdx.y * (WSZ / 2);
    float4 v = *(const float4*)(src + 4 * (long)i);
    dst[2 * i]     = packh2(v.x, v.y);
    dst[2 * i + 1] = packh2(v.z, v.w);
}

// ---------------------------------------------------------------------------
// fp16 GEMM, BK=64 / 3-stage cp.async (this round), fused epilogues (R14):
//  mode 1, z=0/1: rope + rmsnorm -> packed fp16 g_qf/g_kf.
//  mode 1, z=2:   transpose -> fp16 d-major g_vt.
//  mode 0:        proj, fp32 stores.
// Row layout: 64 fp16 = 128 B data + 16 B pad (STRB=144; 144 mod 128 = 16
// => 8 ldmatrix row addresses hit 8 distinct 16B bank groups).
// Accumulation order identical to R14 (k ascending) => bit-identical output.
// ---------------------------------------------------------------------------
#define STRB 144
#define OFF_A 0
#define OFF_B (128*STRB)
#define STAGE_B (2*128*STRB)      // 36864
#define GEMM_SMEM (3*STAGE_B)     // 110592  (x2 CTA = 216KB <= 228KB)
#define SMF_S 133

__global__ __launch_bounds__(256, 2) void gemm_f16(
    const uint32_t* __restrict__ A_u,
    float* __restrict__ Out,
    const float* __restrict__ cosp,
    const float* __restrict__ sinp,
    int mode)
{
    extern __shared__ char smc[];
    const uint32_t sb = s2u(smc);

    const int tid  = threadIdx.x;
    const int warp = tid >> 5;
    const int lane = tid & 31;
    const int wm = warp & 1;
    const int wn = warp >> 1;
    const int gid = lane >> 2;
    const int tig = lane & 3;

    const int m0 = blockIdx.y * 128;
    const int n0 = blockIdx.x * 128;
    const int z  = (mode == 0) ? 3 : blockIdx.z;

    const __half* A_g = (const __half*)A_u;
    const __half* W_g = (const __half*)(g_wf) + (long)z * WSZ;

    float acc[4][4][4];
#pragma unroll
    for (int mi = 0; mi < 4; mi++)
#pragma unroll
        for (int ni = 0; ni < 4; ni++)
#pragma unroll
            for (int c = 0; c < 4; c++) acc[mi][ni][c] = 0.f;

    const int NCH = Cc / 64;   // 20 stages

    // Per-stage: each matrix 128 rows x 8 16B-chunks = 1024 chunks, 4/thread.
    auto issue_stage = [&](int stage, int buf) {
        const int kc0 = stage * 64;
        const uint32_t stB = sb + buf * STAGE_B;
#pragma unroll
        for (int i = 0; i < 4; i++) {
            int c = tid + i * 256;
            int row = c >> 3, kc = c & 7;
            CP_ASYNC16(stB + OFF_A + row * STRB + kc * 16,
                       A_g + (long)(m0 + row) * Cc + kc0 + kc * 8);
        }
#pragma unroll
        for (int i = 0; i < 4; i++) {
            int c = tid + i * 256;
            int row = c >> 3, kc = c & 7;
            CP_ASYNC16(stB + OFF_B + row * STRB + kc * 16,
                       W_g + (long)(n0 + row) * Cc + kc0 + kc * 8);
        }
        CP_COMMIT();
    };

    const uint32_t aRow = wm * 64 + (lane & 7) + ((lane >> 3) & 1) * 8;
    const uint32_t aOff = aRow * STRB + (lane >> 4) * 16;
    const uint32_t bRow = wn * 32 + (lane & 7) + ((lane >> 4) << 3);
    const uint32_t bOff = bRow * STRB + ((lane >> 3) & 1) * 16;

    issue_stage(0, 0);
    issue_stage(1, 1);

    for (int c = 0; c < NCH; c++) {
        if (c + 2 < NCH) issue_stage(c + 2, (c + 2) % 3);
        else             CP_COMMIT();
        CP_WAIT(2);
        __syncthreads();

        const uint32_t base = sb + (c % 3) * STAGE_B;
#pragma unroll
        for (int kk = 0; kk < 4; kk++) {
            const uint32_t ko = kk * 32;
            uint32_t b[4][2];
#pragma unroll
            for (int p = 0; p < 2; p++) {
                uint32_t t0, t1, t2, t3;
                LDSM4(t0, t1, t2, t3, base + OFF_B + bOff + p * (16 * STRB) + ko);
                b[2 * p][0] = t0;     b[2 * p][1] = t1;
                b[2 * p + 1][0] = t2; b[2 * p + 1][1] = t3;
            }
#pragma unroll
            for (int mi = 0; mi < 4; mi++) {
                uint32_t a[4];
                LDSM4(a[0], a[1], a[2], a[3],
                      base + OFF_A + aOff + mi * (16 * STRB) + ko);
#pragma unroll
                for (int ni = 0; ni < 4; ni++)
                    F16_MMA(acc[mi][ni], a, b[ni]);
            }
        }
        __syncthreads();
    }

    if (mode == 0) {
#pragma unroll
        for (int mi = 0; mi < 4; mi++) {
#pragma unroll
            for (int ni = 0; ni < 4; ni++) {
                int r_lo = m0 + wm * 64 + mi * 16 + gid;
                int cn = n0 + wn * 32 + ni * 8 + 2 * tig;
                *(float2*)(Out + (long)r_lo * Cc + cn) =
                    make_float2(acc[mi][ni][0], acc[mi][ni][1]);
                *(float2*)(Out + (long)(r_lo + 8) * Cc + cn) =
                    make_float2(acc[mi][ni][2], acc[mi][ni][3]);
            }
        }
        return;
    }

    // fused q/k/v epilogue (R14-verified)
    float* smf = (float*)smc;
#pragma unroll
    for (int mi = 0; mi < 4; mi++)
#pragma unroll
        for (int ni = 0; ni < 4; ni++) {
            int rl = wm * 64 + mi * 16 + gid;
            int cl = wn * 32 + ni * 8 + 2 * tig;
            smf[rl * SMF_S + cl]           = acc[mi][ni][0];
            smf[rl * SMF_S + cl + 1]       = acc[mi][ni][1];
            smf[(rl + 8) * SMF_S + cl]     = acc[mi][ni][2];
            smf[(rl + 8) * SMF_S + cl + 1] = acc[mi][ni][3];
        }
    __syncthreads();

    const int h_ = n0 >> 7;
    if (z <= 1) {
        uint32_t* dst = (z == 0) ? g_qf : g_kf;
#pragma unroll 1
        for (int pass = 0; pass < 16; pass++) {
            int row = pass * 8 + warp;
            int m = m0 + row;
            int t = m & (Tt - 1);
            int b_ = m >> 11;
            const float* pr = smf + row * SMF_S;
            float a0 = pr[2 * lane],      a1 = pr[2 * lane + 1];
            float a2 = pr[64 + 2 * lane], a3 = pr[64 + 2 * lane + 1];
            float2 cc  = *(const float2*)(cosp + t * 64 + 2 * lane);
            float2 ss2 = *(const float2*)(sinp + t * 64 + 2 * lane);

            float y0 =  a0 * cc.x + a2 * ss2.x;
            float y2 = -a0 * ss2.x + a2 * cc.x;
            float y1 =  a1 * cc.y + a3 * ss2.y;
            float y3 = -a1 * ss2.y + a3 * cc.y;

            float ss = y0 * y0 + y1 * y1 + y2 * y2 + y3 * y3;
#pragma unroll
            for (int o2 = 16; o2; o2 >>= 1)
                ss += __shfl_xor_sync(0xFFFFFFFFu, ss, o2);
            float inv = rsqrtf(ss * (1.0f / 128.0f) + 1e-5f);
            if (z == 0) inv *= SOFT_SCALE;

            long rowg = ((long)(b_ * Hh + h_)) * Tt + t;
            dst[rowg * 64 + lane]      = packh2(y0 * inv, y1 * inv);
            dst[rowg * 64 + 32 + lane] = packh2(y2 * inv, y3 * inv);
        }
    } else {
        int b_ = m0 >> 11;
        int t0 = m0 & (Tt - 1);
        uint32_t* vdst = g_vt + ((long)(b_ * Hh + h_)) * Dd * (Tt / 2) + (t0 >> 1);
        for (int idx = tid; idx < 8192; idx += 256) {
            int d = idx >> 6, tp = idx & 63;
            vdst[(long)d * (Tt / 2) + tp] =
                packh2(smf[(2 * tp) * SMF_S + d], smf[(2 * tp + 1) * SMF_S + d]);
        }
    }
}

// ---------------------------------------------------------------------------
// Flash attention — R14-verified version, restored verbatim (no split-KV).
// fp16 single mma + double-buffered cp.async K/V + ldmatrix fragments.
// ---------------------------------------------------------------------------
#define FQP 68
#define FVP 36
#define FQPB (FQP*4)     // 272 bytes
#define FVPB (FVP*4)     // 144 bytes
#define KSTG (64*FQP)
#define VSTG (128*FVP)
#define FLASH_SMEM_BYTES ((128*FQP + 2*KSTG + 2*VSTG) * 4)   // 106,496

__global__ __launch_bounds__(256, 2) void flash_f16_kernel()
{
    extern __shared__ uint32_t smu[];
    uint32_t* Qf = smu;                          // [128][68]
    const uint32_t sbase = s2u(smu);

    const int tid  = threadIdx.x;
    const int wid  = tid >> 5;
    const int lane = tid & 31;
    const int gid  = lane >> 2;
    const int tig  = lane & 3;

    const int qtile = gridDim.x - 1 - blockIdx.x;
    const int bh = blockIdx.y;
    const int b_ = bh / Hh, h_ = bh % Hh;
    const uint32_t* qsrc = g_qf + (long)bh * Tt * 64;
    const uint32_t* ksrc = g_kf + (long)bh * Tt * 64;
    const uint32_t* vsrc = g_vt + (long)bh * Dd * (Tt / 2);
    const int qb0 = qtile * 128;

    const uint32_t kst_b = sbase + 128 * FQP * 4;
    const uint32_t vst_b = kst_b + 2 * KSTG * 4;

    auto issue_kv = [&](int kt, int buf) {
        const int kbase = kt * 64;
#pragma unroll
        for (int i = 0; i < 4; i++) {
            int c = tid + i * 256;
            int r = c >> 4, col = (c & 15) << 2;
            CP_ASYNC16(kst_b + (buf * KSTG + r * FQP + col) * 4,
                       ksrc + (long)(kbase + r) * 64 + col);
        }
#pragma unroll
        for (int i = 0; i < 4; i++) {
            int c = tid + i * 256;
            int d = c >> 3, col = (c & 7) << 2;
            CP_ASYNC16(vst_b + (buf * VSTG + d * FVP + col) * 4,
                       vsrc + (long)d * (Tt / 2) + (kbase >> 1) + col);
        }
        CP_COMMIT();
    };

    for (int idx = tid; idx < 2048; idx += 256) {
        int r = idx >> 4, c = (idx & 15) << 2;
        uint4 v = *(const uint4*)(qsrc + (long)(qb0 + r) * 64 + c);
        *(uint4*)(Qf + r * FQP + c) = v;
    }

    issue_kv(0, 0);

    float o[16][4];
    float m_[2], l_[2];
#pragma unroll
    for (int ni = 0; ni < 16; ni++)
#pragma unroll
        for (int c = 0; c < 4; c++) o[ni][c] = 0.f;
    m_[0] = m_[1] = -1e30f;
    l_[0] = l_[1] = 0.f;

    const int qrow = wid * 16;
    const int ktmax = 2 * qtile + 2;

    const uint32_t qOff = (uint32_t)(qrow + (lane & 7) + ((lane >> 3) & 1) * 8) * FQPB
                        + (uint32_t)(lane >> 4) * 16;
    const uint32_t kOff = (uint32_t)((lane & 7) + ((lane >> 4) << 3)) * FQPB
                        + (uint32_t)((lane >> 3) & 1) * 16;
    const uint32_t vOff = (uint32_t)((lane & 7) + ((lane >> 4) << 3)) * FVPB
                        + (uint32_t)((lane >> 3) & 1) * 16;

    for (int kt = 0; kt < ktmax; kt++) {
        if (kt + 1 < ktmax) { issue_kv(kt + 1, (kt + 1) & 1); CP_WAIT(1); }
        else                { CP_WAIT(0); }
        __syncthreads();

        const int kbase = kt * 64;
        const uint32_t kf_b = kst_b + (uint32_t)(kt & 1) * KSTG * 4;
        const uint32_t vt_b = vst_b + (uint32_t)(kt & 1) * VSTG * 4;

        float s[8][4];
#pragma unroll
        for (int t = 0; t < 8; t++)
#pragma unroll
            for (int c = 0; c < 4; c++) s[t][c] = 0.f;

#pragma unroll
        for (int j = 0; j < 8; j++) {
            uint32_t a[4];
            LDSM4(a[0], a[1], a[2], a[3], sbase + qOff + j * 32);
            uint32_t b[8][2];
#pragma unroll
            for (int p = 0; p < 4; p++) {
                uint32_t t0, t1, t2, t3;
                LDSM4(t0, t1, t2, t3, kf_b + kOff + p * (16 * FQPB) + j * 32);
                b[2 * p][0] = t0;     b[2 * p][1] = t1;
                b[2 * p + 1][0] = t2; b[2 * p + 1][1] = t3;
            }
#pragma unroll
            for (int ni = 0; ni < 8; ni++)
                F16_MMA(s[ni], a, b[ni]);
        }

        if (kt >= 2 * qtile) {
            int r0g = qb0 + qrow + gid;
#pragma unroll
            for (int t = 0; t < 8; t++) {
                int col = kbase + 8 * t + 2 * tig;
                if (col     > r0g)     s[t][0] = -1e30f;
                if (col + 1 > r0g)     s[t][1] = -1e30f;
                if (col     > r0g + 8) s[t][2] = -1e30f;
                if (col + 1 > r0g + 8) s[t][3] = -1e30f;
            }
        }

#pragma unroll
        for (int r = 0; r < 2; r++) {
            float mx = -1e30f;
#pragma unroll
            for (int t = 0; t < 8; t++)
                mx = fmaxf(mx, fmaxf(s[t][2 * r], s[t][2 * r + 1]));
            mx = fmaxf(mx, __shfl_xor_sync(0xFFFFFFFFu, mx, 1));
            mx = fmaxf(mx, __shfl_xor_sync(0xFFFFFFFFu, mx, 2));
            float mn = fmaxf(m_[r], mx);
            float alpha = __expf(m_[r] - mn);
            float sum = 0.f;
#pragma unroll
            for (int t = 0; t < 8; t++) {
                float p0 = __expf(s[t][2 * r]     - mn);
                float p1 = __expf(s[t][2 * r + 1] - mn);
                s[t][2 * r] = p0; s[t][2 * r + 1] = p1;
                sum += p0 + p1;
            }
            sum += __shfl_xor_sync(0xFFFFFFFFu, sum, 1);
            sum += __shfl_xor_sync(0xFFFFFFFFu, sum, 2);
            l_[r] = l_[r] * alpha + sum;
            m_[r] = mn;
#pragma unroll
            for (int ni = 0; ni < 16; ni++) {
                o[ni][2 * r]     *= alpha;
                o[ni][2 * r + 1] *= alpha;
            }
        }

#pragma unroll
        for (int j = 0; j < 4; j++) {
            uint32_t a[4];
            a[0] = packh2(s[2 * j][0],     s[2 * j][1]);
            a[1] = packh2(s[2 * j][2],     s[2 * j][3]);
            a[2] = packh2(s[2 * j + 1][0], s[2 * j + 1][1]);
            a[3] = packh2(s[2 * j + 1][2], s[2 * j + 1][3]);
#pragma unroll
            for (int p = 0; p < 8; p++) {
                uint32_t t0, t1, t2, t3;
                LDSM4(t0, t1, t2, t3, vt_b + vOff + p * (16 * FVPB) + j * 32);
                uint32_t b0[2] = {t0, t1};
                uint32_t b1[2] = {t2, t3};
                F16_MMA(o[2 * p],     a, b0);
                F16_MMA(o[2 * p + 1], a, b1);
            }
        }
        __syncthreads();
    }

    float inv0 = 1.f / l_[0];
    float inv1 = 1.f / l_[1];
    int r0g = qb0 + qrow + gid;
    long pb0 = (((long)(b_ * Tt + r0g))     * Cc + h_ * Dd) >> 1;
    long pb1 = (((long)(b_ * Tt + r0g + 8)) * Cc + h_ * Dd) >> 1;
#pragma unroll
    for (int ni = 0; ni < 16; ni++) {
        int dp = 4 * ni + tig;
        g_atf[pb0 + dp] = packh2(o[ni][0] * inv0, o[ni][1] * inv0);
        g_atf[pb1 + dp] = packh2(o[ni][2] * inv1, o[ni][3] * inv1);
    }
}

// ---------------------------------------------------------------------------
extern "C" void kernel_launch(void* const* d_in, const int* in_sizes, int n_in,
                              void* d_out, int out_size)
{
    const float* x    = (const float*)d_in[0];
    const float* cosp = (const float*)d_in[1];
    const float* sinp = (const float*)d_in[2];
    const float* Wq   = (const float*)d_in[3];
    const float* Wk   = (const float*)d_in[4];
    const float* Wv   = (const float*)d_in[5];
    const float* Wp   = (const float*)d_in[6];
    float* out = (float*)d_out;

    cudaFuncSetAttribute(gemm_f16,
                         cudaFuncAttributeMaxDynamicSharedMemorySize, GEMM_SMEM);
    cudaFuncSetAttribute(flash_f16_kernel,
                         cudaFuncAttributeMaxDynamicSharedMemorySize,
                         FLASH_SMEM_BYTES);

    uint32_t *xf_p, *atf_p;
    cudaGetSymbolAddress((void**)&xf_p, g_xf);
    cudaGetSymbolAddress((void**)&atf_p, g_atf);

    // 0) Converts
    const int xn4 = Mtot * Cc / 4;
    const int wn4 = WSZ / 4;
    cvt_f16_kernel<<<(xn4 + 255) / 256, 256>>>(x, xf_p, xn4);
    cvt_w_kernel<<<dim3((wn4 + 255) / 256, 4), 256>>>(Wq, Wk, Wv, Wp);

    // 1) Q/K/V projections (BK=64, 3-stage) with fused rope+rmsnorm / vpack
    gemm_f16<<<dim3(Cc / 128, Mtot / 128, 3), 256, GEMM_SMEM>>>(
        xf_p, nullptr, cosp, sinp, 1);
    // 2) Flash attention (R14 version)
    flash_f16_kernel<<<dim3(Tt / 128, BH), 256, FLASH_SMEM_BYTES>>>();
    // 3) Output projection
    gemm_f16<<<dim3(Cc / 128, Mtot / 128, 1), 256, GEMM_SMEM>>>(
        atf_p, out, nullptr, nullptr, 0);
}